// round 1
// baseline (speedup 1.0000x reference)
#include <cuda_runtime.h>

#define B_  2
#define S_  2048
#define H_  1024
#define NH_ 16
#define HD_ 64
#define M_  4096   // B*S

// Scratch (allocation-free rule: __device__ globals)
__device__ float g_q[B_ * NH_ * S_ * HD_];
__device__ float g_k[B_ * NH_ * S_ * HD_];
__device__ float g_v[B_ * NH_ * S_ * HD_];
__device__ float g_ctx[M_ * H_];

// ---------------------------------------------------------------------------
// 128x128x16 fp32 GEMM, 256 threads, 8x8 register tile per thread.
// MODE 0: X @ Wqkv + b -> scatter into g_q/g_k/g_v as [b,n,s,d]
// MODE 1: g_ctx @ Wd + b -> out [4096,1024]
// ---------------------------------------------------------------------------
template <int NCOLS, int MODE>
__global__ __launch_bounds__(256, 2) void gemm128(
    const float* __restrict__ X, const float* __restrict__ W,
    const float* __restrict__ bias, float* __restrict__ out)
{
    __shared__ float As[16][132];   // A transposed: As[k][m], +4 pad
    __shared__ float Bs[16][128];   // Bs[k][n]

    const float* Xp = (MODE == 0) ? X : (const float*)g_ctx;

    const int m0 = blockIdx.y * 128;
    const int n0 = blockIdx.x * 128;
    const int tid = threadIdx.x;
    const int tr = tid >> 4;     // 0..15
    const int tc = tid & 15;     // 0..15

    float acc[8][8];
#pragma unroll
    for (int i = 0; i < 8; i++)
#pragma unroll
        for (int j = 0; j < 8; j++) acc[i][j] = 0.f;

    for (int k0 = 0; k0 < 1024; k0 += 16) {
        // Load A tile 128x16 (transposed into As)
#pragma unroll
        for (int it = 0; it < 2; it++) {
            int id  = tid + 256 * it;
            int row = id >> 2;          // 0..127
            int c4  = (id & 3) * 4;     // 0,4,8,12
            float4 v = *(const float4*)&Xp[(size_t)(m0 + row) * 1024 + k0 + c4];
            As[c4 + 0][row] = v.x;
            As[c4 + 1][row] = v.y;
            As[c4 + 2][row] = v.z;
            As[c4 + 3][row] = v.w;
        }
        // Load B tile 16x128
#pragma unroll
        for (int it = 0; it < 2; it++) {
            int id  = tid + 256 * it;
            int row = id >> 5;          // 0..15
            int c4  = (id & 31) * 4;    // 0..124
            *(float4*)&Bs[row][c4] =
                *(const float4*)&W[(size_t)(k0 + row) * NCOLS + n0 + c4];
        }
        __syncthreads();

#pragma unroll
        for (int kk = 0; kk < 16; kk++) {
            float a[8], b[8];
            *(float4*)&a[0] = *(float4*)&As[kk][tr * 8];
            *(float4*)&a[4] = *(float4*)&As[kk][tr * 8 + 4];
            *(float4*)&b[0] = *(float4*)&Bs[kk][tc * 8];
            *(float4*)&b[4] = *(float4*)&Bs[kk][tc * 8 + 4];
#pragma unroll
            for (int i = 0; i < 8; i++)
#pragma unroll
                for (int j = 0; j < 8; j++) acc[i][j] += a[i] * b[j];
        }
        __syncthreads();
    }

    // Bias
    float bv[8];
#pragma unroll
    for (int j = 0; j < 8; j++) bv[j] = bias[n0 + tc * 8 + j];

#pragma unroll
    for (int i = 0; i < 8; i++) {
        int gr = m0 + tr * 8 + i;
        if (MODE == 0) {
            int bb = gr >> 11;           // batch
            int ss = gr & 2047;          // seq
#pragma unroll
            for (int jj = 0; jj < 8; jj += 4) {
                int gc = n0 + tc * 8 + jj;      // 0..3071
                int which = gc >> 10;
                int h  = gc & 1023;
                int nn = h >> 6;
                int dd = h & 63;
                float4 v;
                v.x = acc[i][jj + 0] + bv[jj + 0];
                v.y = acc[i][jj + 1] + bv[jj + 1];
                v.z = acc[i][jj + 2] + bv[jj + 2];
                v.w = acc[i][jj + 3] + bv[jj + 3];
                float* dst = (which == 0) ? g_q : (which == 1) ? g_k : g_v;
                *(float4*)&dst[(size_t)(((bb * NH_ + nn) * S_ + ss) << 6) + dd] = v;
            }
        } else {
#pragma unroll
            for (int jj = 0; jj < 8; jj += 4) {
                int gc = n0 + tc * 8 + jj;
                float4 v;
                v.x = acc[i][jj + 0] + bv[jj + 0];
                v.y = acc[i][jj + 1] + bv[jj + 1];
                v.z = acc[i][jj + 2] + bv[jj + 2];
                v.w = acc[i][jj + 3] + bv[jj + 3];
                *(float4*)&out[(size_t)gr * 1024 + gc] = v;
            }
        }
    }
}

// ---------------------------------------------------------------------------
// Flash attention: BQ=BK=64, D=64, 256 threads, fp32, causal tile skipping.
// The reference's global-max subtraction is a per-row constant shift ->
// mathematically a no-op for softmax; masked entries (-10000) underflow to 0.
// ---------------------------------------------------------------------------
#define SQ_STRIDE 68   // BQ + 4 pad
__global__ __launch_bounds__(256, 2) void flash_attn()
{
    extern __shared__ float sm[];
    float* Qs  = sm;                 // [64][68] d-major (transposed)
    float* Kst = sm + 64 * 68;       // [64][68] d-major (transposed)
    float* Vs  = sm + 2 * 64 * 68;   // [64][64] k-major
    float* Ps  = sm + 2 * 64 * 68 + 64 * 64;  // [64][68] r-major probs

    const int tid = threadIdx.x;
    const int tr = tid >> 4;   // 0..15 -> q rows tr*4..tr*4+3
    const int tc = tid & 15;   // 0..15 -> k cols / out dims tc*4..tc*4+3
    const int qt   = blockIdx.x;     // q tile 0..31
    const int head = blockIdx.y;     // b*16+n, 0..31
    const int q0 = qt * 64;

    const float* Qg = g_q + (size_t)head * (S_ * HD_);
    const float* Kg = g_k + (size_t)head * (S_ * HD_);
    const float* Vg = g_v + (size_t)head * (S_ * HD_);

    // Load Q tile transposed: Qs[d][r]
#pragma unroll
    for (int it = 0; it < 4; it++) {
        int id = tid + 256 * it;
        int r  = id >> 4;
        int d4 = (id & 15) * 4;
        float4 v = *(const float4*)&Qg[(size_t)(q0 + r) * 64 + d4];
        Qs[(d4 + 0) * SQ_STRIDE + r] = v.x;
        Qs[(d4 + 1) * SQ_STRIDE + r] = v.y;
        Qs[(d4 + 2) * SQ_STRIDE + r] = v.z;
        Qs[(d4 + 3) * SQ_STRIDE + r] = v.w;
    }

    float m_i[4], l_i[4], acc[4][4];
#pragma unroll
    for (int i = 0; i < 4; i++) {
        m_i[i] = -1e30f;
        l_i[i] = 0.f;
#pragma unroll
        for (int j = 0; j < 4; j++) acc[i][j] = 0.f;
    }
    __syncthreads();

    const float scale = 0.125f;  // 1/sqrt(64)

    for (int t = 0; t <= qt; t++) {
        int k0 = t * 64;
        // Load K transposed + V direct
#pragma unroll
        for (int it = 0; it < 4; it++) {
            int id = tid + 256 * it;
            int c  = id >> 4;
            int d4 = (id & 15) * 4;
            float4 kv = *(const float4*)&Kg[(size_t)(k0 + c) * 64 + d4];
            Kst[(d4 + 0) * SQ_STRIDE + c] = kv.x;
            Kst[(d4 + 1) * SQ_STRIDE + c] = kv.y;
            Kst[(d4 + 2) * SQ_STRIDE + c] = kv.z;
            Kst[(d4 + 3) * SQ_STRIDE + c] = kv.w;
            float4 vv = *(const float4*)&Vg[(size_t)(k0 + c) * 64 + d4];
            *(float4*)&Vs[c * 64 + d4] = vv;
        }
        __syncthreads();

        // scores S = Q @ K^T  (4x4 per thread)
        float s[4][4];
#pragma unroll
        for (int i = 0; i < 4; i++)
#pragma unroll
            for (int j = 0; j < 4; j++) s[i][j] = 0.f;

#pragma unroll 8
        for (int kk = 0; kk < 64; kk++) {
            float4 a = *(float4*)&Qs[kk * SQ_STRIDE + tr * 4];
            float4 b = *(float4*)&Kst[kk * SQ_STRIDE + tc * 4];
            s[0][0] += a.x * b.x; s[0][1] += a.x * b.y; s[0][2] += a.x * b.z; s[0][3] += a.x * b.w;
            s[1][0] += a.y * b.x; s[1][1] += a.y * b.y; s[1][2] += a.y * b.z; s[1][3] += a.y * b.w;
            s[2][0] += a.z * b.x; s[2][1] += a.z * b.y; s[2][2] += a.z * b.z; s[2][3] += a.z * b.w;
            s[3][0] += a.w * b.x; s[3][1] += a.w * b.y; s[3][2] += a.w * b.z; s[3][3] += a.w * b.w;
        }

        // scale + causal mask (only the diagonal tile needs masking)
        if (t == qt) {
#pragma unroll
            for (int i = 0; i < 4; i++)
#pragma unroll
                for (int j = 0; j < 4; j++)
                    s[i][j] = (tc * 4 + j <= tr * 4 + i) ? s[i][j] * scale : -1e30f;
        } else {
#pragma unroll
            for (int i = 0; i < 4; i++)
#pragma unroll
                for (int j = 0; j < 4; j++) s[i][j] *= scale;
        }

        // online softmax (row groups = 16 lanes sharing tr)
#pragma unroll
        for (int i = 0; i < 4; i++) {
            float rm = fmaxf(fmaxf(s[i][0], s[i][1]), fmaxf(s[i][2], s[i][3]));
#pragma unroll
            for (int off = 8; off >= 1; off >>= 1)
                rm = fmaxf(rm, __shfl_xor_sync(0xffffffffu, rm, off, 16));
            float newm = fmaxf(m_i[i], rm);
            float corr = __expf(m_i[i] - newm);
            float rs = 0.f;
#pragma unroll
            for (int j = 0; j < 4; j++) {
                float p = __expf(s[i][j] - newm);
                Ps[(tr * 4 + i) * SQ_STRIDE + tc * 4 + j] = p;
                rs += p;
            }
#pragma unroll
            for (int off = 8; off >= 1; off >>= 1)
                rs += __shfl_xor_sync(0xffffffffu, rs, off, 16);
            l_i[i] = l_i[i] * corr + rs;
            m_i[i] = newm;
#pragma unroll
            for (int j = 0; j < 4; j++) acc[i][j] *= corr;
        }
        __syncthreads();

        // acc += P @ V  (vectorized over k in chunks of 4)
#pragma unroll 4
        for (int kk4 = 0; kk4 < 16; kk4++) {
            float4 pa0 = *(float4*)&Ps[(tr * 4 + 0) * SQ_STRIDE + kk4 * 4];
            float4 pa1 = *(float4*)&Ps[(tr * 4 + 1) * SQ_STRIDE + kk4 * 4];
            float4 pa2 = *(float4*)&Ps[(tr * 4 + 2) * SQ_STRIDE + kk4 * 4];
            float4 pa3 = *(float4*)&Ps[(tr * 4 + 3) * SQ_STRIDE + kk4 * 4];
            float4 vb0 = *(float4*)&Vs[(kk4 * 4 + 0) * 64 + tc * 4];
            float4 vb1 = *(float4*)&Vs[(kk4 * 4 + 1) * 64 + tc * 4];
            float4 vb2 = *(float4*)&Vs[(kk4 * 4 + 2) * 64 + tc * 4];
            float4 vb3 = *(float4*)&Vs[(kk4 * 4 + 3) * 64 + tc * 4];
            acc[0][0] += pa0.x*vb0.x + pa0.y*vb1.x + pa0.z*vb2.x + pa0.w*vb3.x;
            acc[0][1] += pa0.x*vb0.y + pa0.y*vb1.y + pa0.z*vb2.y + pa0.w*vb3.y;
            acc[0][2] += pa0.x*vb0.z + pa0.y*vb1.z + pa0.z*vb2.z + pa0.w*vb3.z;
            acc[0][3] += pa0.x*vb0.w + pa0.y*vb1.w + pa0.z*vb2.w + pa0.w*vb3.w;
            acc[1][0] += pa1.x*vb0.x + pa1.y*vb1.x + pa1.z*vb2.x + pa1.w*vb3.x;
            acc[1][1] += pa1.x*vb0.y + pa1.y*vb1.y + pa1.z*vb2.y + pa1.w*vb3.y;
            acc[1][2] += pa1.x*vb0.z + pa1.y*vb1.z + pa1.z*vb2.z + pa1.w*vb3.z;
            acc[1][3] += pa1.x*vb0.w + pa1.y*vb1.w + pa1.z*vb2.w + pa1.w*vb3.w;
            acc[2][0] += pa2.x*vb0.x + pa2.y*vb1.x + pa2.z*vb2.x + pa2.w*vb3.x;
            acc[2][1] += pa2.x*vb0.y + pa2.y*vb1.y + pa2.z*vb2.y + pa2.w*vb3.y;
            acc[2][2] += pa2.x*vb0.z + pa2.y*vb1.z + pa2.z*vb2.z + pa2.w*vb3.z;
            acc[2][3] += pa2.x*vb0.w + pa2.y*vb1.w + pa2.z*vb2.w + pa2.w*vb3.w;
            acc[3][0] += pa3.x*vb0.x + pa3.y*vb1.x + pa3.z*vb2.x + pa3.w*vb3.x;
            acc[3][1] += pa3.x*vb0.y + pa3.y*vb1.y + pa3.z*vb2.y + pa3.w*vb3.y;
            acc[3][2] += pa3.x*vb0.z + pa3.y*vb1.z + pa3.z*vb2.z + pa3.w*vb3.z;
            acc[3][3] += pa3.x*vb0.w + pa3.y*vb1.w + pa3.z*vb2.w + pa3.w*vb3.w;
        }
        __syncthreads();
    }

    // Epilogue -> ctx[b, s, n*64 + d]
    const int bb = head >> 4;
    const int nn = head & 15;
#pragma unroll
    for (int i = 0; i < 4; i++) {
        float inv = 1.f / l_i[i];
        int srow = q0 + tr * 4 + i;
        float4 v;
        v.x = acc[i][0] * inv;
        v.y = acc[i][1] * inv;
        v.z = acc[i][2] * inv;
        v.w = acc[i][3] * inv;
        *(float4*)&g_ctx[(size_t)(bb * S_ + srow) * H_ + nn * 64 + tc * 4] = v;
    }
}

// ---------------------------------------------------------------------------
extern "C" void kernel_launch(void* const* d_in, const int* in_sizes, int n_in,
                              void* d_out, int out_size)
{
    const float* X    = (const float*)d_in[0];   // hidden_states [2,2048,1024]
    // d_in[1] = ltor_mask (unused: causal handled analytically)
    const float* Wqkv = (const float*)d_in[2];   // [1024,3072]
    const float* bqkv = (const float*)d_in[3];   // [3072]
    const float* Wd   = (const float*)d_in[4];   // [1024,1024]
    const float* bd   = (const float*)d_in[5];   // [1024]
    float* out = (float*)d_out;

    // 1. QKV projection -> g_q/g_k/g_v in [head][s][d]
    gemm128<3072, 0><<<dim3(24, 32), 256>>>(X, Wqkv, bqkv, nullptr);

    // 2. Flash attention -> g_ctx
    const int smem = (2 * 64 * 68 + 64 * 64 + 64 * 68) * (int)sizeof(float);
    cudaFuncSetAttribute(flash_attn, cudaFuncAttributeMaxDynamicSharedMemorySize, smem);
    flash_attn<<<dim3(32, 32), 256, smem>>>();

    // 3. Output projection -> out
    gemm128<1024, 1><<<dim3(8, 32), 256>>>(nullptr, Wd, bd, out);
}

// round 4
// speedup vs baseline: 2.5070x; 2.5070x over previous
#include <cuda_runtime.h>
#include <cuda_bf16.h>
#include <cstdint>

#define B_  2
#define S_  2048
#define H_  1024
#define NH_ 16
#define HD_ 64
#define M_  4096   // B*S

// ---------------------------------------------------------------------------
// Device scratch (allocation-free rule)
// ---------------------------------------------------------------------------
__device__ __nv_bfloat16 ga_hi[M_ * H_],      ga_lo[M_ * H_];       // X split
__device__ __nv_bfloat16 gwq_hi[3072 * 1024], gwq_lo[3072 * 1024];  // Wqkv^T split
__device__ __nv_bfloat16 gwd_hi[1024 * 1024], gwd_lo[1024 * 1024];  // Wd^T split
#define QKV_ELEMS (B_ * NH_ * S_ * HD_)
__device__ __nv_bfloat16 gq_hi[QKV_ELEMS], gq_lo[QKV_ELEMS];        // q (pre-scaled)
__device__ __nv_bfloat16 gk_hi[QKV_ELEMS], gk_lo[QKV_ELEMS];
__device__ __nv_bfloat16 gv_hi[QKV_ELEMS], gv_lo[QKV_ELEMS];
__device__ __nv_bfloat16 gctx_hi[M_ * H_],   gctx_lo[M_ * H_];      // ctx split

// ---------------------------------------------------------------------------
// Helpers
// ---------------------------------------------------------------------------
__device__ __forceinline__ uint32_t smem_u32(const void* p) {
    uint32_t a;
    asm("{ .reg .u64 t; cvta.to.shared.u64 t, %1; cvt.u32.u64 %0, t; }" : "=r"(a) : "l"(p));
    return a;
}
__device__ __forceinline__ void cp16(uint32_t dst, const void* src) {
    asm volatile("cp.async.cg.shared.global [%0], [%1], 16;\n" :: "r"(dst), "l"(src));
}
#define CP_COMMIT() asm volatile("cp.async.commit_group;\n" ::: "memory")
#define CP_WAIT(n)  asm volatile("cp.async.wait_group %0;\n" :: "n"(n) : "memory")

__device__ __forceinline__ void ldsm4(uint32_t* r, uint32_t a) {
    asm volatile("ldmatrix.sync.aligned.m8n8.x4.shared.b16 {%0,%1,%2,%3}, [%4];"
                 : "=r"(r[0]), "=r"(r[1]), "=r"(r[2]), "=r"(r[3]) : "r"(a));
}
__device__ __forceinline__ void ldsm4t(uint32_t* r, uint32_t a) {
    asm volatile("ldmatrix.sync.aligned.m8n8.x4.trans.shared.b16 {%0,%1,%2,%3}, [%4];"
                 : "=r"(r[0]), "=r"(r[1]), "=r"(r[2]), "=r"(r[3]) : "r"(a));
}
// D = A(16x16 bf16) * B(16x8 bf16) + D (fp32)
__device__ __forceinline__ void mma16816(float* c, const uint32_t* a, const uint32_t* b) {
    asm volatile(
        "mma.sync.aligned.m16n8k16.row.col.f32.bf16.bf16.f32 "
        "{%0,%1,%2,%3}, {%4,%5,%6,%7}, {%8,%9}, {%0,%1,%2,%3};"
        : "+f"(c[0]), "+f"(c[1]), "+f"(c[2]), "+f"(c[3])
        : "r"(a[0]), "r"(a[1]), "r"(a[2]), "r"(a[3]), "r"(b[0]), "r"(b[1]));
}
__device__ __forceinline__ void split_bf16(float x, __nv_bfloat16& h, __nv_bfloat16& l) {
    h = __float2bfloat16(x);
    l = __float2bfloat16(x - __bfloat162float(h));
}
__device__ __forceinline__ uint32_t pack2(__nv_bfloat16 lo, __nv_bfloat16 hi) {
    __nv_bfloat162 t; t.x = lo; t.y = hi;
    return *(uint32_t*)&t;
}

// ---------------------------------------------------------------------------
// Conversion kernels
// ---------------------------------------------------------------------------
__global__ void convX(const float* __restrict__ X) {
    size_t i = ((size_t)blockIdx.x * 256 + threadIdx.x) * 4;
    float4 v = *(const float4*)&X[i];
    __nv_bfloat16 h0, h1, h2, h3, l0, l1, l2, l3;
    split_bf16(v.x, h0, l0); split_bf16(v.y, h1, l1);
    split_bf16(v.z, h2, l2); split_bf16(v.w, h3, l3);
    *(uint32_t*)&ga_hi[i]     = pack2(h0, h1);
    *(uint32_t*)&ga_hi[i + 2] = pack2(h2, h3);
    *(uint32_t*)&ga_lo[i]     = pack2(l0, l1);
    *(uint32_t*)&ga_lo[i + 2] = pack2(l2, l3);
}

// W [1024][NC] -> Wt split [NC][1024]
template <int NC>
__global__ void convW(const float* __restrict__ W) {
    __shared__ float t[32][33];
    __nv_bfloat16* hi = (NC == 3072) ? gwq_hi : gwd_hi;
    __nv_bfloat16* lo = (NC == 3072) ? gwq_lo : gwd_lo;
    const int tx = threadIdx.x, ty = threadIdx.y;      // 32 x 8
    const int n0 = blockIdx.x * 32, k0 = blockIdx.y * 32;
#pragma unroll
    for (int j = 0; j < 4; j++)
        t[ty + 8 * j][tx] = W[(size_t)(k0 + ty + 8 * j) * NC + n0 + tx];
    __syncthreads();
#pragma unroll
    for (int j = 0; j < 4; j++) {
        float v = t[tx][ty + 8 * j];
        __nv_bfloat16 h, l;
        split_bf16(v, h, l);
        size_t o = (size_t)(n0 + ty + 8 * j) * 1024 + k0 + tx;
        hi[o] = h;
        lo[o] = l;
    }
}

// ---------------------------------------------------------------------------
// mma.sync bf16x3 GEMM: 128x128 tile, 8 warps (4x2), K-chunks of 64.
// A[m][k], B[n][k] both bf16 hi/lo row-major (k inner, stride 1024).
// MODE 0: QKV -> scatter bf16 hi/lo into gq/gk/gv (q scaled 1/8).
// MODE 1: ctx @ Wd -> out fp32 + bias.
// ---------------------------------------------------------------------------
#define GPAD 72                     // padded row length (elems)
#define GHALF (128 * GPAD * 2)      // one operand-half tile: 18432 B
#define G_STAGE (4 * GHALF)         // Ah, Al, Bh, Bl : 73728 B
#define GEMM_SMEM (2 * G_STAGE)     // 147456 B

template <int MODE>
__global__ __launch_bounds__(256) void gemm_mma(const float* __restrict__ bias,
                                                float* __restrict__ out)
{
    extern __shared__ char smem[];
    const uint32_t sb = smem_u32(smem);
    const int tid = threadIdx.x, wid = tid >> 5, lane = tid & 31;
    const int wm = wid >> 1, wn = wid & 1;     // warp tile: rows wm*32, cols wn*64
    const int m0 = blockIdx.y * 128, n0 = blockIdx.x * 128;

    const __nv_bfloat16* gAh = ((MODE == 0) ? ga_hi : gctx_hi) + (size_t)m0 * 1024;
    const __nv_bfloat16* gAl = ((MODE == 0) ? ga_lo : gctx_lo) + (size_t)m0 * 1024;
    const __nv_bfloat16* gBh = ((MODE == 0) ? gwq_hi : gwd_hi) + (size_t)n0 * 1024;
    const __nv_bfloat16* gBl = ((MODE == 0) ? gwq_lo : gwd_lo) + (size_t)n0 * 1024;

    float c[2][8][4];
#pragma unroll
    for (int a = 0; a < 2; a++)
#pragma unroll
        for (int b = 0; b < 8; b++)
#pragma unroll
            for (int d = 0; d < 4; d++) c[a][b][d] = 0.f;

    // chunk loader: 128 rows x 64 cols per operand-half
    auto load_chunk = [&](int ch, int stage) {
        uint32_t base = sb + stage * G_STAGE;
        const __nv_bfloat16* srcs[4] = {gAh, gAl, gBh, gBl};
#pragma unroll
        for (int half = 0; half < 4; half++) {
            uint32_t hb = base + half * GHALF;
            const __nv_bfloat16* g = srcs[half] + ch * 64;
#pragma unroll
            for (int it = 0; it < 4; it++) {
                int id  = tid + 256 * it;          // 0..1023
                int row = id >> 3, cc = id & 7;
                cp16(hb + (uint32_t)(row * GPAD + cc * 8) * 2,
                     g + (size_t)row * 1024 + cc * 8);
            }
        }
    };

    load_chunk(0, 0);
    CP_COMMIT();

    for (int ch = 0; ch < 16; ch++) {
        if (ch < 15) {
            load_chunk(ch + 1, (ch + 1) & 1);
            CP_COMMIT();
            CP_WAIT(1);
        } else {
            CP_WAIT(0);
        }
        __syncthreads();

        uint32_t base = sb + (ch & 1) * G_STAGE;
        uint32_t sAh = base, sAl = base + GHALF, sBh = base + 2 * GHALF, sBl = base + 3 * GHALF;

        // lane addressing
        const int ar = wm * 32 + (lane & 15);
        const int ac_off = (lane >> 4) * 8;
        const int br = wn * 64 + (lane & 7) + ((lane >> 4) << 3);
        const int bc_off = ((lane >> 3) & 1) * 8;

#pragma unroll
        for (int ks = 0; ks < 4; ks++) {
            uint32_t ah[2][4], al[2][4];
            int ac = ks * 16 + ac_off;
#pragma unroll
            for (int mb = 0; mb < 2; mb++) {
                uint32_t off = (uint32_t)((ar + mb * 16) * GPAD + ac) * 2;
                ldsm4(ah[mb], sAh + off);
                ldsm4(al[mb], sAl + off);
            }
            int bc = ks * 16 + bc_off;
#pragma unroll
            for (int nbp = 0; nbp < 4; nbp++) {
                uint32_t bh[4], bl[4];
                uint32_t off = (uint32_t)((br + nbp * 16) * GPAD + bc) * 2;
                ldsm4(bh, sBh + off);
                ldsm4(bl, sBl + off);
#pragma unroll
                for (int mb = 0; mb < 2; mb++) {
#pragma unroll
                    for (int nn = 0; nn < 2; nn++) {
                        float* cc = c[mb][nbp * 2 + nn];
                        mma16816(cc, ah[mb], bh + nn * 2);
                        mma16816(cc, ah[mb], bl + nn * 2);
                        mma16816(cc, al[mb], bh + nn * 2);
                    }
                }
            }
        }
        __syncthreads();
    }

    // epilogue
#pragma unroll
    for (int mb = 0; mb < 2; mb++) {
#pragma unroll
        for (int h = 0; h < 2; h++) {
            int gr = m0 + wm * 32 + mb * 16 + (lane >> 2) + 8 * h;
#pragma unroll
            for (int nb = 0; nb < 8; nb++) {
                int gc = n0 + wn * 64 + nb * 8 + (lane & 3) * 2;
                float v0 = c[mb][nb][2 * h + 0] + bias[gc];
                float v1 = c[mb][nb][2 * h + 1] + bias[gc + 1];
                if (MODE == 0) {
                    int bb = gr >> 11, ssq = gr & 2047;
                    int which = gc >> 10, hh = gc & 1023;
                    int nn = hh >> 6, dd = hh & 63;
                    if (which == 0) { v0 *= 0.125f; v1 *= 0.125f; }  // fold 1/sqrt(64)
                    __nv_bfloat16 h0, h1, l0, l1;
                    split_bf16(v0, h0, l0);
                    split_bf16(v1, h1, l1);
                    size_t idx = ((size_t)((bb * NH_ + nn) * S_ + ssq) << 6) + dd;
                    __nv_bfloat16* dh = (which == 0) ? gq_hi : (which == 1) ? gk_hi : gv_hi;
                    __nv_bfloat16* dl = (which == 0) ? gq_lo : (which == 1) ? gk_lo : gv_lo;
                    *(uint32_t*)&dh[idx] = pack2(h0, h1);
                    *(uint32_t*)&dl[idx] = pack2(l0, l1);
                } else {
                    float2 v; v.x = v0; v.y = v1;
                    *(float2*)&out[(size_t)gr * 1024 + gc] = v;
                }
            }
        }
    }
}

// ---------------------------------------------------------------------------
// Flash attention on mma.sync: BQ=128, BK=64, D=64, 8 warps.
// Reference's global-max shift is a per-row constant -> softmax no-op;
// masked entries underflow to 0 -> plain causal flash attention.
// ---------------------------------------------------------------------------
#define FQ_BYTES (128 * GPAD * 2)        // one Q half: 18432
#define FKV_HALF (64 * GPAD * 2)         // 9216
#define F_STAGE (4 * FKV_HALF)           // Kh,Kl,Vh,Vl: 36864
#define FLASH_SMEM (2 * FQ_BYTES + 2 * F_STAGE)   // 110592

__global__ __launch_bounds__(256) void flash_mma()
{
    extern __shared__ char smem[];
    const uint32_t sb = smem_u32(smem);
    const uint32_t sQh = sb, sQl = sb + FQ_BYTES;
    const uint32_t sKV = sb + 2 * FQ_BYTES;

    const int tid = threadIdx.x, wid = tid >> 5, lane = tid & 31;
    const int bq = (gridDim.x - 1) - blockIdx.x;   // big tiles first
    const int head = blockIdx.y;
    const int q0 = bq * 128;
    const int ntiles = 2 * bq + 2;

    const size_t hoff = (size_t)head * (S_ * HD_);

    // prologue: Q tile (hi/lo) + KV tile 0
    {
#pragma unroll
        for (int it = 0; it < 8; it++) {
            int id = tid + 256 * it;               // 0..2047
            int row = id >> 4, cc = id & 15;
            uint32_t dst = ((cc < 8) ? sQh : sQl) + (uint32_t)(row * GPAD + (cc & 7) * 8) * 2;
            const __nv_bfloat16* g = ((cc < 8) ? gq_hi : gq_lo) + hoff + (size_t)(q0 + row) * 64 + (cc & 7) * 8;
            cp16(dst, g);
        }
    }
    auto load_kv = [&](int t, int stage) {
        uint32_t base = sKV + stage * F_STAGE;
        int k0 = t * 64;
#pragma unroll
        for (int it = 0; it < 8; it++) {
            int id = tid + 256 * it;               // 0..2047
            int arr = id >> 9, rem = id & 511;
            int row = rem >> 3, cc = rem & 7;
            const __nv_bfloat16* g =
                (arr == 0) ? gk_hi : (arr == 1) ? gk_lo : (arr == 2) ? gv_hi : gv_lo;
            cp16(base + arr * FKV_HALF + (uint32_t)(row * GPAD + cc * 8) * 2,
                 g + hoff + (size_t)(k0 + row) * 64 + cc * 8);
        }
    };
    load_kv(0, 0);
    CP_COMMIT();

    float m_i[2] = {-1e30f, -1e30f};
    float l_i[2] = {0.f, 0.f};
    float ctx[8][4];
#pragma unroll
    for (int nb = 0; nb < 8; nb++)
#pragma unroll
        for (int d = 0; d < 4; d++) ctx[nb][d] = 0.f;

    uint32_t qf[4][2][4];   // [kstep][hi/lo][regs]
    const int qrow_base = q0 + wid * 16 + (lane >> 2);

    for (int t = 0; t < ntiles; t++) {
        if (t + 1 < ntiles) {
            load_kv(t + 1, (t + 1) & 1);
            CP_COMMIT();
            CP_WAIT(1);
        } else {
            CP_WAIT(0);
        }
        __syncthreads();

        if (t == 0) {
            // Q fragments (held all kernel)
            const int ar = wid * 16 + (lane & 15);
            const int acoff = (lane >> 4) * 8;
#pragma unroll
            for (int ks = 0; ks < 4; ks++) {
                uint32_t off = (uint32_t)(ar * GPAD + ks * 16 + acoff) * 2;
                ldsm4(qf[ks][0], sQh + off);
                ldsm4(qf[ks][1], sQl + off);
            }
        }

        uint32_t base = sKV + (t & 1) * F_STAGE;
        uint32_t sKh = base, sKl = base + FKV_HALF;
        uint32_t sVh = base + 2 * FKV_HALF, sVl = base + 3 * FKV_HALF;

        // S = Qs @ K^T  (scale folded into Q)
        float s[8][4];
#pragma unroll
        for (int nb = 0; nb < 8; nb++)
#pragma unroll
            for (int d = 0; d < 4; d++) s[nb][d] = 0.f;

        const int kr = (lane & 7) + ((lane >> 4) << 3);
        const int kcoff = ((lane >> 3) & 1) * 8;
#pragma unroll
        for (int nbp = 0; nbp < 4; nbp++) {
#pragma unroll
            for (int ks = 0; ks < 4; ks++) {
                uint32_t bh[4], bl[4];
                uint32_t off = (uint32_t)((nbp * 16 + kr) * GPAD + ks * 16 + kcoff) * 2;
                ldsm4(bh, sKh + off);
                ldsm4(bl, sKl + off);
#pragma unroll
                for (int nn = 0; nn < 2; nn++) {
                    float* cc = s[nbp * 2 + nn];
                    mma16816(cc, qf[ks][0], bh + nn * 2);
                    mma16816(cc, qf[ks][0], bl + nn * 2);
                    mma16816(cc, qf[ks][1], bh + nn * 2);
                }
            }
        }

        // causal mask (only tiles straddling this warp's rows)
        if (t * 64 + 63 > q0 + wid * 16) {
            int cb = t * 64 + (lane & 3) * 2;
#pragma unroll
            for (int nb = 0; nb < 8; nb++)
#pragma unroll
                for (int h = 0; h < 2; h++)
#pragma unroll
                    for (int j = 0; j < 2; j++)
                        if (cb + nb * 8 + j > qrow_base + 8 * h)
                            s[nb][2 * h + j] = -1e30f;
        }

        // online softmax; s becomes P
#pragma unroll
        for (int h = 0; h < 2; h++) {
            float rm = -1e30f;
#pragma unroll
            for (int nb = 0; nb < 8; nb++)
                rm = fmaxf(rm, fmaxf(s[nb][2 * h], s[nb][2 * h + 1]));
            rm = fmaxf(rm, __shfl_xor_sync(0xffffffffu, rm, 1));
            rm = fmaxf(rm, __shfl_xor_sync(0xffffffffu, rm, 2));
            float nm = fmaxf(m_i[h], rm);
            float corr = __expf(m_i[h] - nm);
            m_i[h] = nm;
            float rs = 0.f;
#pragma unroll
            for (int nb = 0; nb < 8; nb++) {
                float p0 = __expf(s[nb][2 * h] - nm);
                float p1 = __expf(s[nb][2 * h + 1] - nm);
                s[nb][2 * h] = p0;
                s[nb][2 * h + 1] = p1;
                rs += p0 + p1;
            }
            rs += __shfl_xor_sync(0xffffffffu, rs, 1);
            rs += __shfl_xor_sync(0xffffffffu, rs, 2);
            l_i[h] = l_i[h] * corr + rs;
#pragma unroll
            for (int nb = 0; nb < 8; nb++) {
                ctx[nb][2 * h] *= corr;
                ctx[nb][2 * h + 1] *= corr;
            }
        }

        // P -> A fragments (hi/lo)
        uint32_t pf[4][4], pl[4][4];
#pragma unroll
        for (int kb = 0; kb < 4; kb++) {
#pragma unroll
            for (int r = 0; r < 4; r++) {
                int nb = kb * 2 + (r >> 1);
                int i0 = (r & 1) * 2;       // r even: h=0 pair; r odd: h=1 pair
                float v0 = s[nb][i0], v1 = s[nb][i0 + 1];
                __nv_bfloat16 h0, h1, l0, l1;
                split_bf16(v0, h0, l0);
                split_bf16(v1, h1, l1);
                pf[kb][r] = pack2(h0, h1);
                pl[kb][r] = pack2(l0, l1);
            }
        }

        // ctx += P @ V
        const int vr = lane & 15;
        const int vcoff = (lane >> 4) * 8;
#pragma unroll
        for (int nbp = 0; nbp < 4; nbp++) {
#pragma unroll
            for (int kb = 0; kb < 4; kb++) {
                uint32_t bh[4], bl[4];
                uint32_t off = (uint32_t)((kb * 16 + vr) * GPAD + nbp * 16 + vcoff) * 2;
                ldsm4t(bh, sVh + off);
                ldsm4t(bl, sVl + off);
#pragma unroll
                for (int nn = 0; nn < 2; nn++) {
                    float* cc = ctx[nbp * 2 + nn];
                    mma16816(cc, pf[kb], bh + nn * 2);
                    mma16816(cc, pf[kb], bl + nn * 2);
                    mma16816(cc, pl[kb], bh + nn * 2);
                }
            }
        }
        __syncthreads();
    }

    // epilogue: ctx/l -> gctx hi/lo at [b, s, head*64 + d]
    const int bb = head >> 4, nnh = head & 15;
#pragma unroll
    for (int h = 0; h < 2; h++) {
        float inv = 1.f / l_i[h];
        int srow = q0 + wid * 16 + (lane >> 2) + 8 * h;
        size_t rbase = (size_t)(bb * S_ + srow) * H_ + nnh * 64;
#pragma unroll
        for (int nb = 0; nb < 8; nb++) {
            int dd = nb * 8 + (lane & 3) * 2;
            float v0 = ctx[nb][2 * h] * inv;
            float v1 = ctx[nb][2 * h + 1] * inv;
            __nv_bfloat16 h0, h1, l0, l1;
            split_bf16(v0, h0, l0);
            split_bf16(v1, h1, l1);
            *(uint32_t*)&gctx_hi[rbase + dd] = pack2(h0, h1);
            *(uint32_t*)&gctx_lo[rbase + dd] = pack2(l0, l1);
        }
    }
}

// ---------------------------------------------------------------------------
extern "C" void kernel_launch(void* const* d_in, const int* in_sizes, int n_in,
                              void* d_out, int out_size)
{
    const float* X    = (const float*)d_in[0];   // [2,2048,1024]
    // d_in[1] = ltor_mask (causal handled analytically)
    const float* Wqkv = (const float*)d_in[2];   // [1024,3072]
    const float* bqkv = (const float*)d_in[3];   // [3072]
    const float* Wd   = (const float*)d_in[4];   // [1024,1024]
    const float* bd   = (const float*)d_in[5];   // [1024]
    float* out = (float*)d_out;

    // 0. fp32 -> bf16 hi/lo splits (+ weight transposes)
    convX<<<4096, 256>>>(X);
    convW<3072><<<dim3(96, 32), dim3(32, 8)>>>(Wqkv);
    convW<1024><<<dim3(32, 32), dim3(32, 8)>>>(Wd);

    // 1. QKV projection -> gq/gk/gv bf16 hi/lo (q pre-scaled)
    cudaFuncSetAttribute(gemm_mma<0>, cudaFuncAttributeMaxDynamicSharedMemorySize, GEMM_SMEM);
    gemm_mma<0><<<dim3(24, 32), 256, GEMM_SMEM>>>(bqkv, nullptr);

    // 2. Flash attention -> gctx hi/lo
    cudaFuncSetAttribute(flash_mma, cudaFuncAttributeMaxDynamicSharedMemorySize, FLASH_SMEM);
    flash_mma<<<dim3(16, 32), 256, FLASH_SMEM>>>();

    // 3. Output projection -> out
    cudaFuncSetAttribute(gemm_mma<1>, cudaFuncAttributeMaxDynamicSharedMemorySize, GEMM_SMEM);
    gemm_mma<1><<<dim3(8, 32), 256, GEMM_SMEM>>>(bd, out);
}

// round 10
// speedup vs baseline: 2.6051x; 1.0391x over previous
#include <cuda_runtime.h>
#include <cuda_bf16.h>
#include <cstdint>

#define B_  2
#define S_  2048
#define H_  1024
#define NH_ 16
#define HD_ 64
#define M_  4096   // B*S

// ---------------------------------------------------------------------------
// Device scratch
// ---------------------------------------------------------------------------
__device__ __nv_bfloat16 ga_hi[M_ * H_],      ga_lo[M_ * H_];
__device__ __nv_bfloat16 gwq_hi[3072 * 1024], gwq_lo[3072 * 1024];
__device__ __nv_bfloat16 gwd_hi[1024 * 1024], gwd_lo[1024 * 1024];
#define QKV_ELEMS (B_ * NH_ * S_ * HD_)
__device__ __nv_bfloat16 gq_hi[QKV_ELEMS], gq_lo[QKV_ELEMS];   // q pre-scaled 1/8
__device__ __nv_bfloat16 gk_hi[QKV_ELEMS], gk_lo[QKV_ELEMS];
__device__ __nv_bfloat16 gv_hi[QKV_ELEMS], gv_lo[QKV_ELEMS];
__device__ __nv_bfloat16 gctx_hi[M_ * H_],   gctx_lo[M_ * H_];

// ---------------------------------------------------------------------------
// Helpers
// ---------------------------------------------------------------------------
__device__ __forceinline__ uint32_t smem_u32(const void* p) {
    uint32_t a;
    asm("{ .reg .u64 t; cvta.to.shared.u64 t, %1; cvt.u32.u64 %0, t; }" : "=r"(a) : "l"(p));
    return a;
}
__device__ __forceinline__ void cp16(uint32_t dst, const void* src) {
    asm volatile("cp.async.cg.shared.global [%0], [%1], 16;\n" :: "r"(dst), "l"(src));
}
#define CP_COMMIT() asm volatile("cp.async.commit_group;\n" ::: "memory")
#define CP_WAIT(n)  asm volatile("cp.async.wait_group %0;\n" :: "n"(n) : "memory")

__device__ __forceinline__ void ldsm4(uint32_t* r, uint32_t a) {
    asm volatile("ldmatrix.sync.aligned.m8n8.x4.shared.b16 {%0,%1,%2,%3}, [%4];"
                 : "=r"(r[0]), "=r"(r[1]), "=r"(r[2]), "=r"(r[3]) : "r"(a));
}
__device__ __forceinline__ void ldsm4t(uint32_t* r, uint32_t a) {
    asm volatile("ldmatrix.sync.aligned.m8n8.x4.trans.shared.b16 {%0,%1,%2,%3}, [%4];"
                 : "=r"(r[0]), "=r"(r[1]), "=r"(r[2]), "=r"(r[3]) : "r"(a));
}
__device__ __forceinline__ void mma16816(float* c, const uint32_t* a, const uint32_t* b) {
    asm volatile(
        "mma.sync.aligned.m16n8k16.row.col.f32.bf16.bf16.f32 "
        "{%0,%1,%2,%3}, {%4,%5,%6,%7}, {%8,%9}, {%0,%1,%2,%3};"
        : "+f"(c[0]), "+f"(c[1]), "+f"(c[2]), "+f"(c[3])
        : "r"(a[0]), "r"(a[1]), "r"(a[2]), "r"(a[3]), "r"(b[0]), "r"(b[1]));
}
__device__ __forceinline__ void split_bf16(float x, __nv_bfloat16& h, __nv_bfloat16& l) {
    h = __float2bfloat16(x);
    l = __float2bfloat16(x - __bfloat162float(h));
}
__device__ __forceinline__ uint32_t pack2(__nv_bfloat16 lo, __nv_bfloat16 hi) {
    __nv_bfloat162 t; t.x = lo; t.y = hi;
    return *(uint32_t*)&t;
}

// ---------------------------------------------------------------------------
// Conversion kernels
// ---------------------------------------------------------------------------
__global__ void convX(const float* __restrict__ X) {
    size_t i = ((size_t)blockIdx.x * 256 + threadIdx.x) * 4;
    float4 v = *(const float4*)&X[i];
    __nv_bfloat16 h0, h1, h2, h3, l0, l1, l2, l3;
    split_bf16(v.x, h0, l0); split_bf16(v.y, h1, l1);
    split_bf16(v.z, h2, l2); split_bf16(v.w, h3, l3);
    *(uint32_t*)&ga_hi[i]     = pack2(h0, h1);
    *(uint32_t*)&ga_hi[i + 2] = pack2(h2, h3);
    *(uint32_t*)&ga_lo[i]     = pack2(l0, l1);
    *(uint32_t*)&ga_lo[i + 2] = pack2(l2, l3);
}

template <int NC>
__global__ void convW(const float* __restrict__ W) {
    __shared__ float t[32][33];
    __nv_bfloat16* hi = (NC == 3072) ? gwq_hi : gwd_hi;
    __nv_bfloat16* lo = (NC == 3072) ? gwq_lo : gwd_lo;
    const int tx = threadIdx.x, ty = threadIdx.y;      // 32 x 8
    const int n0 = blockIdx.x * 32, k0 = blockIdx.y * 32;
#pragma unroll
    for (int j = 0; j < 4; j++)
        t[ty + 8 * j][tx] = W[(size_t)(k0 + ty + 8 * j) * NC + n0 + tx];
    __syncthreads();
#pragma unroll
    for (int j = 0; j < 4; j++) {
        float v = t[tx][ty + 8 * j];
        __nv_bfloat16 h, l;
        split_bf16(v, h, l);
        size_t o = (size_t)(n0 + ty + 8 * j) * 1024 + k0 + tx;
        hi[o] = h;
        lo[o] = l;
    }
}

// ---------------------------------------------------------------------------
// GEMM: 128x128 CTA tile, 4 warps (2x2) of 64x64, K-chunks of 32, 2 stages.
// Row stride 40 elems = 80B (16B-aligned; 8 rows permute all 16B groups).
// ---------------------------------------------------------------------------
#define GSTR 40                          // padded row stride (elems), 80B
#define GHALF (128 * GSTR * 2)           // 10240 B
#define G_STAGE (4 * GHALF)              // Ah Al Bh Bl : 40960 B
#define GEMM_SMEM (2 * G_STAGE)          // 81920 B -> 2 CTAs/SM

template <int MODE>
__global__ __launch_bounds__(128, 2) void gemm_mma(const float* __restrict__ bias,
                                                   float* __restrict__ out)
{
    extern __shared__ char smem[];
    const uint32_t sb = smem_u32(smem);
    const int tid = threadIdx.x, wid = tid >> 5, lane = tid & 31;
    const int wm = wid >> 1, wn = wid & 1;     // 64-row, 64-col warp tile
    const int m0 = blockIdx.y * 128, n0 = blockIdx.x * 128;

    const __nv_bfloat16* gAh = ((MODE == 0) ? ga_hi : gctx_hi) + (size_t)m0 * 1024;
    const __nv_bfloat16* gAl = ((MODE == 0) ? ga_lo : gctx_lo) + (size_t)m0 * 1024;
    const __nv_bfloat16* gBh = ((MODE == 0) ? gwq_hi : gwd_hi) + (size_t)n0 * 1024;
    const __nv_bfloat16* gBl = ((MODE == 0) ? gwq_lo : gwd_lo) + (size_t)n0 * 1024;

    float c[4][8][4];
#pragma unroll
    for (int a = 0; a < 4; a++)
#pragma unroll
        for (int b = 0; b < 8; b++)
#pragma unroll
            for (int d = 0; d < 4; d++) c[a][b][d] = 0.f;

    // one chunk = 128 rows x 32 k-cols per operand-half
    auto load_chunk = [&](int ch, int stage) {
        uint32_t base = sb + stage * G_STAGE;
        const __nv_bfloat16* srcs[4] = {gAh, gAl, gBh, gBl};
#pragma unroll
        for (int half = 0; half < 4; half++) {
            uint32_t hb = base + half * GHALF;
            const __nv_bfloat16* g = srcs[half] + ch * 32;
#pragma unroll
            for (int it = 0; it < 4; it++) {
                int id  = tid + 128 * it;           // 0..511
                int row = id >> 2, cc = id & 3;
                cp16(hb + (uint32_t)(row * GSTR + cc * 8) * 2,
                     g + (size_t)row * 1024 + cc * 8);
            }
        }
    };

    load_chunk(0, 0);
    CP_COMMIT();

    const int ar = wm * 64 + (lane & 15);
    const int ac_off = (lane >> 4) * 8;
    const int br = wn * 64 + (lane & 7) + ((lane >> 4) << 3);
    const int bc_off = ((lane >> 3) & 1) * 8;

    for (int ch = 0; ch < 32; ch++) {
        if (ch < 31) {
            load_chunk(ch + 1, (ch + 1) & 1);
            CP_COMMIT();
            CP_WAIT(1);          // chunk ch complete
        } else {
            CP_WAIT(0);
        }
        __syncthreads();

        uint32_t base = sb + (ch & 1) * G_STAGE;
        uint32_t sAh = base, sAl = base + GHALF;
        uint32_t sBh = base + 2 * GHALF, sBl = base + 3 * GHALF;

#pragma unroll
        for (int ks = 0; ks < 2; ks++) {
            uint32_t ah[4][4], al[4][4];
            int ac = ks * 16 + ac_off;
#pragma unroll
            for (int mb = 0; mb < 4; mb++) {
                uint32_t off = (uint32_t)((ar + mb * 16) * GSTR + ac) * 2;
                ldsm4(ah[mb], sAh + off);
                ldsm4(al[mb], sAl + off);
            }
            int bc = ks * 16 + bc_off;
#pragma unroll
            for (int nbp = 0; nbp < 4; nbp++) {
                uint32_t bh[4], bl[4];
                uint32_t off = (uint32_t)((br + nbp * 16) * GSTR + bc) * 2;
                ldsm4(bh, sBh + off);
                ldsm4(bl, sBl + off);
#pragma unroll
                for (int mb = 0; mb < 4; mb++) {
#pragma unroll
                    for (int nn = 0; nn < 2; nn++) {
                        float* cc = c[mb][nbp * 2 + nn];
                        mma16816(cc, ah[mb], bh + nn * 2);
                        mma16816(cc, ah[mb], bl + nn * 2);
                        mma16816(cc, al[mb], bh + nn * 2);
                    }
                }
            }
        }
        __syncthreads();
    }

    // epilogue
#pragma unroll
    for (int mb = 0; mb < 4; mb++) {
#pragma unroll
        for (int h = 0; h < 2; h++) {
            int gr = m0 + wm * 64 + mb * 16 + (lane >> 2) + 8 * h;
#pragma unroll
            for (int nb = 0; nb < 8; nb++) {
                int gc = n0 + wn * 64 + nb * 8 + (lane & 3) * 2;
                float v0 = c[mb][nb][2 * h + 0] + bias[gc];
                float v1 = c[mb][nb][2 * h + 1] + bias[gc + 1];
                if (MODE == 0) {
                    int bb = gr >> 11, ssq = gr & 2047;
                    int which = gc >> 10, hh = gc & 1023;
                    int nn = hh >> 6, dd = hh & 63;
                    if (which == 0) { v0 *= 0.125f; v1 *= 0.125f; }
                    __nv_bfloat16 h0, h1, l0, l1;
                    split_bf16(v0, h0, l0);
                    split_bf16(v1, h1, l1);
                    size_t idx = ((size_t)((bb * NH_ + nn) * S_ + ssq) << 6) + dd;
                    __nv_bfloat16* dh = (which == 0) ? gq_hi : (which == 1) ? gk_hi : gv_hi;
                    __nv_bfloat16* dl = (which == 0) ? gq_lo : (which == 1) ? gk_lo : gv_lo;
                    *(uint32_t*)&dh[idx] = pack2(h0, h1);
                    *(uint32_t*)&dl[idx] = pack2(l0, l1);
                } else {
                    float2 v; v.x = v0; v.y = v1;
                    *(float2*)&out[(size_t)gr * 1024 + gc] = v;
                }
            }
        }
    }
}

// ---------------------------------------------------------------------------
// Flash attention: BQ=128, BK=64, 4 warps of 32 q-rows, double-buffered KV.
// Reference's global-max shift is a softmax no-op; -10000 mask underflows to 0
// -> plain causal flash attention with tile skipping.
// ---------------------------------------------------------------------------
#define FSTR 72
#define FQH  (128 * FSTR * 2)            // 18432
#define FKVH (64 * FSTR * 2)             // 9216
#define F_STAGE (4 * FKVH)               // 36864
#define FLASH_SMEM (2 * FQH + 2 * F_STAGE)   // 110592

__global__ __launch_bounds__(128, 2) void flash_mma()
{
    extern __shared__ char smem[];
    const uint32_t sb = smem_u32(smem);
    const uint32_t sQh = sb, sQl = sb + FQH;
    const uint32_t sKV = sb + 2 * FQH;

    const int tid = threadIdx.x, wid = tid >> 5, lane = tid & 31;
    const int bq = (gridDim.x - 1) - blockIdx.x;
    const int head = blockIdx.y;
    const int q0 = bq * 128;
    const int ntiles = 2 * bq + 2;
    const size_t hoff = (size_t)head * (S_ * HD_);

    // Q tile (hi/lo)
#pragma unroll
    for (int it = 0; it < 16; it++) {
        int id = tid + 128 * it;               // 0..2047
        int row = id >> 4, cc = id & 15;
        uint32_t dst = ((cc < 8) ? sQh : sQl) + (uint32_t)(row * FSTR + (cc & 7) * 8) * 2;
        const __nv_bfloat16* g = ((cc < 8) ? gq_hi : gq_lo)
                                 + hoff + (size_t)(q0 + row) * 64 + (cc & 7) * 8;
        cp16(dst, g);
    }
    auto load_kv = [&](int t, int stage) {
        uint32_t base = sKV + stage * F_STAGE;
        int k0 = t * 64;
#pragma unroll
        for (int it = 0; it < 16; it++) {
            int id = tid + 128 * it;           // 0..2047
            int arr = id >> 9, rem = id & 511;
            int row = rem >> 3, cc = rem & 7;
            const __nv_bfloat16* g =
                (arr == 0) ? gk_hi : (arr == 1) ? gk_lo : (arr == 2) ? gv_hi : gv_lo;
            cp16(base + arr * FKVH + (uint32_t)(row * FSTR + cc * 8) * 2,
                 g + hoff + (size_t)(k0 + row) * 64 + cc * 8);
        }
    };
    load_kv(0, 0);
    CP_COMMIT();

    float m_i[2][2], l_i[2][2];
#pragma unroll
    for (int mb = 0; mb < 2; mb++)
#pragma unroll
        for (int h = 0; h < 2; h++) { m_i[mb][h] = -1e30f; l_i[mb][h] = 0.f; }
    float ctx[2][8][4];
#pragma unroll
    for (int mb = 0; mb < 2; mb++)
#pragma unroll
        for (int nb = 0; nb < 8; nb++)
#pragma unroll
            for (int d = 0; d < 4; d++) ctx[mb][nb][d] = 0.f;

    const int ar = wid * 32 + (lane & 15);
    const int acoff = (lane >> 4) * 8;
    const int kr = (lane & 7) + ((lane >> 4) << 3);
    const int kcoff = ((lane >> 3) & 1) * 8;
    const int vr = lane & 15;
    const int vcoff = (lane >> 4) * 8;
    const int qrow0 = q0 + wid * 32 + (lane >> 2);

    for (int t = 0; t < ntiles; t++) {
        if (t + 1 < ntiles) {
            load_kv(t + 1, (t + 1) & 1);
            CP_COMMIT();
            CP_WAIT(1);
        } else {
            CP_WAIT(0);
        }
        __syncthreads();

        uint32_t base = sKV + (t & 1) * F_STAGE;
        uint32_t sKh = base, sKl = base + FKVH;
        uint32_t sVh = base + 2 * FKVH, sVl = base + 3 * FKVH;

        // S = Q @ K^T (scale folded into Q)
        float s[2][8][4];
#pragma unroll
        for (int mb = 0; mb < 2; mb++)
#pragma unroll
            for (int nb = 0; nb < 8; nb++)
#pragma unroll
                for (int d = 0; d < 4; d++) s[mb][nb][d] = 0.f;

#pragma unroll
        for (int ks = 0; ks < 4; ks++) {
            uint32_t qh[2][4], ql[2][4];
#pragma unroll
            for (int mb = 0; mb < 2; mb++) {
                uint32_t off = (uint32_t)((ar + mb * 16) * FSTR + ks * 16 + acoff) * 2;
                ldsm4(qh[mb], sQh + off);
                ldsm4(ql[mb], sQl + off);
            }
#pragma unroll
            for (int nbp = 0; nbp < 4; nbp++) {
                uint32_t bh[4], bl[4];
                uint32_t off = (uint32_t)((nbp * 16 + kr) * FSTR + ks * 16 + kcoff) * 2;
                ldsm4(bh, sKh + off);
                ldsm4(bl, sKl + off);
#pragma unroll
                for (int mb = 0; mb < 2; mb++) {
#pragma unroll
                    for (int nn = 0; nn < 2; nn++) {
                        float* cc = s[mb][nbp * 2 + nn];
                        mma16816(cc, qh[mb], bh + nn * 2);
                        mma16816(cc, qh[mb], bl + nn * 2);
                        mma16816(cc, ql[mb], bh + nn * 2);
                    }
                }
            }
        }

        // causal mask
        if (t * 64 + 63 > q0 + wid * 32) {
            int cb = t * 64 + (lane & 3) * 2;
#pragma unroll
            for (int mb = 0; mb < 2; mb++)
#pragma unroll
                for (int nb = 0; nb < 8; nb++)
#pragma unroll
                    for (int h = 0; h < 2; h++)
#pragma unroll
                        for (int j = 0; j < 2; j++)
                            if (cb + nb * 8 + j > qrow0 + mb * 16 + 8 * h)
                                s[mb][nb][2 * h + j] = -1e30f;
        }

        // online softmax
#pragma unroll
        for (int mb = 0; mb < 2; mb++) {
#pragma unroll
            for (int h = 0; h < 2; h++) {
                float rm = -1e30f;
#pragma unroll
                for (int nb = 0; nb < 8; nb++)
                    rm = fmaxf(rm, fmaxf(s[mb][nb][2 * h], s[mb][nb][2 * h + 1]));
                rm = fmaxf(rm, __shfl_xor_sync(0xffffffffu, rm, 1));
                rm = fmaxf(rm, __shfl_xor_sync(0xffffffffu, rm, 2));
                float nm = fmaxf(m_i[mb][h], rm);
                float corr = __expf(m_i[mb][h] - nm);
                m_i[mb][h] = nm;
                float rs = 0.f;
#pragma unroll
                for (int nb = 0; nb < 8; nb++) {
                    float p0 = __expf(s[mb][nb][2 * h] - nm);
                    float p1 = __expf(s[mb][nb][2 * h + 1] - nm);
                    s[mb][nb][2 * h] = p0;
                    s[mb][nb][2 * h + 1] = p1;
                    rs += p0 + p1;
                }
                rs += __shfl_xor_sync(0xffffffffu, rs, 1);
                rs += __shfl_xor_sync(0xffffffffu, rs, 2);
                l_i[mb][h] = l_i[mb][h] * corr + rs;
#pragma unroll
                for (int nb = 0; nb < 8; nb++) {
                    ctx[mb][nb][2 * h] *= corr;
                    ctx[mb][nb][2 * h + 1] *= corr;
                }
            }
        }

        // P -> A fragments (hi/lo)
        uint32_t pf[2][4][4], pl[2][4][4];
#pragma unroll
        for (int mb = 0; mb < 2; mb++)
#pragma unroll
            for (int kb = 0; kb < 4; kb++)
#pragma unroll
                for (int r = 0; r < 4; r++) {
                    int nb = kb * 2 + (r >> 1);
                    int i0 = (r & 1) * 2;
                    float v0 = s[mb][nb][i0], v1 = s[mb][nb][i0 + 1];
                    __nv_bfloat16 h0, h1, l0, l1;
                    split_bf16(v0, h0, l0);
                    split_bf16(v1, h1, l1);
                    pf[mb][kb][r] = pack2(h0, h1);
                    pl[mb][kb][r] = pack2(l0, l1);
                }

        // ctx += P @ V
#pragma unroll
        for (int nbp = 0; nbp < 4; nbp++) {
#pragma unroll
            for (int kb = 0; kb < 4; kb++) {
                uint32_t bh[4], bl[4];
                uint32_t off = (uint32_t)((kb * 16 + vr) * FSTR + nbp * 16 + vcoff) * 2;
                ldsm4t(bh, sVh + off);
                ldsm4t(bl, sVl + off);
#pragma unroll
                for (int mb = 0; mb < 2; mb++) {
#pragma unroll
                    for (int nn = 0; nn < 2; nn++) {
                        float* cc = ctx[mb][nbp * 2 + nn];
                        mma16816(cc, pf[mb][kb], bh + nn * 2);
                        mma16816(cc, pf[mb][kb], bl + nn * 2);
                        mma16816(cc, pl[mb][kb], bh + nn * 2);
                    }
                }
            }
        }
        __syncthreads();
    }

    // epilogue
    const int bb = head >> 4, nnh = head & 15;
#pragma unroll
    for (int mb = 0; mb < 2; mb++)
#pragma unroll
        for (int h = 0; h < 2; h++) {
            float inv = 1.f / l_i[mb][h];
            int srow = q0 + wid * 32 + mb * 16 + (lane >> 2) + 8 * h;
            size_t rbase = (size_t)(bb * S_ + srow) * H_ + nnh * 64;
#pragma unroll
            for (int nb = 0; nb < 8; nb++) {
                int dd = nb * 8 + (lane & 3) * 2;
                float v0 = ctx[mb][nb][2 * h] * inv;
                float v1 = ctx[mb][nb][2 * h + 1] * inv;
                __nv_bfloat16 h0, h1, l0, l1;
                split_bf16(v0, h0, l0);
                split_bf16(v1, h1, l1);
                *(uint32_t*)&gctx_hi[rbase + dd] = pack2(h0, h1);
                *(uint32_t*)&gctx_lo[rbase + dd] = pack2(l0, l1);
            }
        }
}

// ---------------------------------------------------------------------------
extern "C" void kernel_launch(void* const* d_in, const int* in_sizes, int n_in,
                              void* d_out, int out_size)
{
    const float* X    = (const float*)d_in[0];
    const float* Wqkv = (const float*)d_in[2];
    const float* bqkv = (const float*)d_in[3];
    const float* Wd   = (const float*)d_in[4];
    const float* bd   = (const float*)d_in[5];
    float* out = (float*)d_out;

    convX<<<4096, 256>>>(X);
    convW<3072><<<dim3(96, 32), dim3(32, 8)>>>(Wqkv);
    convW<1024><<<dim3(32, 32), dim3(32, 8)>>>(Wd);

    cudaFuncSetAttribute(gemm_mma<0>, cudaFuncAttributeMaxDynamicSharedMemorySize, GEMM_SMEM);
    gemm_mma<0><<<dim3(24, 32), 128, GEMM_SMEM>>>(bqkv, nullptr);

    cudaFuncSetAttribute(flash_mma, cudaFuncAttributeMaxDynamicSharedMemorySize, FLASH_SMEM);
    flash_mma<<<dim3(16, 32), 128, FLASH_SMEM>>>();

    cudaFuncSetAttribute(gemm_mma<1>, cudaFuncAttributeMaxDynamicSharedMemorySize, GEMM_SMEM);
    gemm_mma<1><<<dim3(8, 32), 128, GEMM_SMEM>>>(bd, out);
}

// round 16
// speedup vs baseline: 3.7430x; 1.4368x over previous
#include <cuda_runtime.h>
#include <cuda_fp16.h>
#include <cstdint>

#define B_  2
#define S_  2048
#define H_  1024
#define NH_ 16
#define HD_ 64
#define M_  4096   // B*S

// ---------------------------------------------------------------------------
// Device scratch (fp16x2 scheme: A-side single fp16, B-side hi+lo fp16)
// ---------------------------------------------------------------------------
__device__ __half ga[M_ * H_];                                  // X fp16
__device__ __half gwq_hi[3072 * 1024], gwq_lo[3072 * 1024];     // Wqkv^T hi/lo
__device__ __half gwd_hi[1024 * 1024], gwd_lo[1024 * 1024];     // Wd^T hi/lo
#define QKV_ELEMS (B_ * NH_ * S_ * HD_)
__device__ __half gq[QKV_ELEMS];                                // q fp16 (pre-scaled 1/8)
__device__ __half gk_hi[QKV_ELEMS], gk_lo[QKV_ELEMS];
__device__ __half gv_hi[QKV_ELEMS], gv_lo[QKV_ELEMS];
__device__ __half gctx[M_ * H_];                                // ctx fp16

// ---------------------------------------------------------------------------
// Helpers
// ---------------------------------------------------------------------------
__device__ __forceinline__ uint32_t smem_u32(const void* p) {
    uint32_t a;
    asm("{ .reg .u64 t; cvta.to.shared.u64 t, %1; cvt.u32.u64 %0, t; }" : "=r"(a) : "l"(p));
    return a;
}
__device__ __forceinline__ void cp16(uint32_t dst, const void* src) {
    asm volatile("cp.async.cg.shared.global [%0], [%1], 16;\n" :: "r"(dst), "l"(src));
}
#define CP_COMMIT() asm volatile("cp.async.commit_group;\n" ::: "memory")
#define CP_WAIT(n)  asm volatile("cp.async.wait_group %0;\n" :: "n"(n) : "memory")

__device__ __forceinline__ void ldsm4(uint32_t* r, uint32_t a) {
    asm volatile("ldmatrix.sync.aligned.m8n8.x4.shared.b16 {%0,%1,%2,%3}, [%4];"
                 : "=r"(r[0]), "=r"(r[1]), "=r"(r[2]), "=r"(r[3]) : "r"(a));
}
__device__ __forceinline__ void ldsm4t(uint32_t* r, uint32_t a) {
    asm volatile("ldmatrix.sync.aligned.m8n8.x4.trans.shared.b16 {%0,%1,%2,%3}, [%4];"
                 : "=r"(r[0]), "=r"(r[1]), "=r"(r[2]), "=r"(r[3]) : "r"(a));
}
// f16 MMA, fp32 accumulate
__device__ __forceinline__ void mma16816(float* c, const uint32_t* a, const uint32_t* b) {
    asm volatile(
        "mma.sync.aligned.m16n8k16.row.col.f32.f16.f16.f32 "
        "{%0,%1,%2,%3}, {%4,%5,%6,%7}, {%8,%9}, {%0,%1,%2,%3};"
        : "+f"(c[0]), "+f"(c[1]), "+f"(c[2]), "+f"(c[3])
        : "r"(a[0]), "r"(a[1]), "r"(a[2]), "r"(a[3]), "r"(b[0]), "r"(b[1]));
}
__device__ __forceinline__ void split_f16(float x, __half& h, __half& l) {
    h = __float2half(x);
    l = __float2half(x - __half2float(h));
}
__device__ __forceinline__ uint32_t pack2h(__half lo, __half hi) {
    __half2 t; t.x = lo; t.y = hi;
    return *(uint32_t*)&t;
}

// ---------------------------------------------------------------------------
// Conversion kernels
// ---------------------------------------------------------------------------
__global__ void convX(const float* __restrict__ X) {
    size_t i = ((size_t)blockIdx.x * 256 + threadIdx.x) * 4;
    float4 v = *(const float4*)&X[i];
    *(uint32_t*)&ga[i]     = pack2h(__float2half(v.x), __float2half(v.y));
    *(uint32_t*)&ga[i + 2] = pack2h(__float2half(v.z), __float2half(v.w));
}

// W [1024][NC] -> Wt hi/lo [NC][1024]
template <int NC>
__global__ void convW(const float* __restrict__ W) {
    __shared__ float t[32][33];
    __half* hi = (NC == 3072) ? gwq_hi : gwd_hi;
    __half* lo = (NC == 3072) ? gwq_lo : gwd_lo;
    const int tx = threadIdx.x, ty = threadIdx.y;      // 32 x 8
    const int n0 = blockIdx.x * 32, k0 = blockIdx.y * 32;
#pragma unroll
    for (int j = 0; j < 4; j++)
        t[ty + 8 * j][tx] = W[(size_t)(k0 + ty + 8 * j) * NC + n0 + tx];
    __syncthreads();
#pragma unroll
    for (int j = 0; j < 4; j++) {
        float v = t[tx][ty + 8 * j];
        __half h, l;
        split_f16(v, h, l);
        size_t o = (size_t)(n0 + ty + 8 * j) * 1024 + k0 + tx;
        hi[o] = h;
        lo[o] = l;
    }
}

// ---------------------------------------------------------------------------
// GEMM (fp16x2): 128x128 CTA tile, 4 warps of 64x64, K-chunks 32, 2 stages.
// Per product: Ah*Bh + Ah*Bl (B-side corrected). 2 MMAs instead of 3.
// ---------------------------------------------------------------------------
#define GSTR 40                          // 80B row stride (16B-aligned, odd 16B groups)
#define GHALF (128 * GSTR * 2)           // 10240 B
#define G_STAGE (3 * GHALF)              // A, Bh, Bl : 30720 B
#define GEMM_SMEM (2 * G_STAGE)          // 61440 B

template <int MODE>
__global__ __launch_bounds__(128, 2) void gemm_mma(const float* __restrict__ bias,
                                                   float* __restrict__ out)
{
    extern __shared__ char smem[];
    const uint32_t sb = smem_u32(smem);
    const int tid = threadIdx.x, wid = tid >> 5, lane = tid & 31;
    const int wm = wid >> 1, wn = wid & 1;
    const int m0 = blockIdx.y * 128, n0 = blockIdx.x * 128;

    const __half* gA  = ((MODE == 0) ? ga : gctx) + (size_t)m0 * 1024;
    const __half* gBh = ((MODE == 0) ? gwq_hi : gwd_hi) + (size_t)n0 * 1024;
    const __half* gBl = ((MODE == 0) ? gwq_lo : gwd_lo) + (size_t)n0 * 1024;

    float c[4][8][4];
#pragma unroll
    for (int a = 0; a < 4; a++)
#pragma unroll
        for (int b = 0; b < 8; b++)
#pragma unroll
            for (int d = 0; d < 4; d++) c[a][b][d] = 0.f;

    auto load_chunk = [&](int ch, int stage) {
        uint32_t base = sb + stage * G_STAGE;
        const __half* srcs[3] = {gA, gBh, gBl};
#pragma unroll
        for (int half = 0; half < 3; half++) {
            uint32_t hb = base + half * GHALF;
            const __half* g = srcs[half] + ch * 32;
#pragma unroll
            for (int it = 0; it < 4; it++) {
                int id  = tid + 128 * it;           // 0..511
                int row = id >> 2, cc = id & 3;
                cp16(hb + (uint32_t)(row * GSTR + cc * 8) * 2,
                     g + (size_t)row * 1024 + cc * 8);
            }
        }
    };

    load_chunk(0, 0);
    CP_COMMIT();

    const int ar = wm * 64 + (lane & 15);
    const int ac_off = (lane >> 4) * 8;
    const int br = wn * 64 + (lane & 7) + ((lane >> 4) << 3);
    const int bc_off = ((lane >> 3) & 1) * 8;

    for (int ch = 0; ch < 32; ch++) {
        if (ch < 31) {
            load_chunk(ch + 1, (ch + 1) & 1);
            CP_COMMIT();
            CP_WAIT(1);
        } else {
            CP_WAIT(0);
        }
        __syncthreads();

        uint32_t base = sb + (ch & 1) * G_STAGE;
        uint32_t sA = base, sBh = base + GHALF, sBl = base + 2 * GHALF;

#pragma unroll
        for (int ks = 0; ks < 2; ks++) {
            uint32_t ah[4][4];
            int ac = ks * 16 + ac_off;
#pragma unroll
            for (int mb = 0; mb < 4; mb++)
                ldsm4(ah[mb], sA + (uint32_t)((ar + mb * 16) * GSTR + ac) * 2);
            int bc = ks * 16 + bc_off;
#pragma unroll
            for (int nbp = 0; nbp < 4; nbp++) {
                uint32_t bh[4], bl[4];
                uint32_t off = (uint32_t)((br + nbp * 16) * GSTR + bc) * 2;
                ldsm4(bh, sBh + off);
                ldsm4(bl, sBl + off);
#pragma unroll
                for (int mb = 0; mb < 4; mb++) {
#pragma unroll
                    for (int nn = 0; nn < 2; nn++) {
                        float* cc = c[mb][nbp * 2 + nn];
                        mma16816(cc, ah[mb], bh + nn * 2);
                        mma16816(cc, ah[mb], bl + nn * 2);
                    }
                }
            }
        }
        __syncthreads();
    }

    // epilogue
#pragma unroll
    for (int mb = 0; mb < 4; mb++) {
#pragma unroll
        for (int h = 0; h < 2; h++) {
            int gr = m0 + wm * 64 + mb * 16 + (lane >> 2) + 8 * h;
#pragma unroll
            for (int nb = 0; nb < 8; nb++) {
                int gc = n0 + wn * 64 + nb * 8 + (lane & 3) * 2;
                float v0 = c[mb][nb][2 * h + 0] + bias[gc];
                float v1 = c[mb][nb][2 * h + 1] + bias[gc + 1];
                if (MODE == 0) {
                    int bb = gr >> 11, ssq = gr & 2047;
                    int which = gc >> 10, hh = gc & 1023;
                    int nn = hh >> 6, dd = hh & 63;
                    size_t idx = ((size_t)((bb * NH_ + nn) * S_ + ssq) << 6) + dd;
                    if (which == 0) {
                        // q: single fp16, pre-scaled by 1/sqrt(64)
                        *(uint32_t*)&gq[idx] =
                            pack2h(__float2half(v0 * 0.125f), __float2half(v1 * 0.125f));
                    } else {
                        __half h0, h1, l0, l1;
                        split_f16(v0, h0, l0);
                        split_f16(v1, h1, l1);
                        __half* dh = (which == 1) ? gk_hi : gv_hi;
                        __half* dl = (which == 1) ? gk_lo : gv_lo;
                        *(uint32_t*)&dh[idx] = pack2h(h0, h1);
                        *(uint32_t*)&dl[idx] = pack2h(l0, l1);
                    }
                } else {
                    float2 v; v.x = v0; v.y = v1;
                    *(float2*)&out[(size_t)gr * 1024 + gc] = v;
                }
            }
        }
    }
}

// ---------------------------------------------------------------------------
// Flash attention (fp16x2): BQ=128, BK=64, 4 warps of 32 q-rows.
// QK: qh*(kh+kl); PV: Ph*(vh+vl). Q fragments hoisted into registers.
// Reference's global-max shift is a softmax no-op; -10000 mask underflows to 0.
// ---------------------------------------------------------------------------
#define FSTR 72
#define FQH  (128 * FSTR * 2)            // 18432 (single Q buffer)
#define FKVH (64 * FSTR * 2)             // 9216
#define F_STAGE (4 * FKVH)               // Kh Kl Vh Vl : 36864
#define FLASH_SMEM (FQH + 2 * F_STAGE)   // 92160

__global__ __launch_bounds__(128, 2) void flash_mma()
{
    extern __shared__ char smem[];
    const uint32_t sb = smem_u32(smem);
    const uint32_t sQ = sb;
    const uint32_t sKV = sb + FQH;

    const int tid = threadIdx.x, wid = tid >> 5, lane = tid & 31;
    const int bq = (gridDim.x - 1) - blockIdx.x;
    const int head = blockIdx.y;
    const int q0 = bq * 128;
    const int ntiles = 2 * bq + 2;
    const size_t hoff = (size_t)head * (S_ * HD_);

    // Q tile (fp16, single)
#pragma unroll
    for (int it = 0; it < 8; it++) {
        int id = tid + 128 * it;               // 0..1023
        int row = id >> 3, cc = id & 7;
        cp16(sQ + (uint32_t)(row * FSTR + cc * 8) * 2,
             gq + hoff + (size_t)(q0 + row) * 64 + cc * 8);
    }
    auto load_kv = [&](int t, int stage) {
        uint32_t base = sKV + stage * F_STAGE;
        int k0 = t * 64;
#pragma unroll
        for (int it = 0; it < 16; it++) {
            int id = tid + 128 * it;           // 0..2047
            int arr = id >> 9, rem = id & 511;
            int row = rem >> 3, cc = rem & 7;
            const __half* g =
                (arr == 0) ? gk_hi : (arr == 1) ? gk_lo : (arr == 2) ? gv_hi : gv_lo;
            cp16(base + arr * FKVH + (uint32_t)(row * FSTR + cc * 8) * 2,
                 g + hoff + (size_t)(k0 + row) * 64 + cc * 8);
        }
    };
    load_kv(0, 0);
    CP_COMMIT();

    float m_i[2][2], l_i[2][2];
#pragma unroll
    for (int mb = 0; mb < 2; mb++)
#pragma unroll
        for (int h = 0; h < 2; h++) { m_i[mb][h] = -1e30f; l_i[mb][h] = 0.f; }
    float ctx[2][8][4];
#pragma unroll
    for (int mb = 0; mb < 2; mb++)
#pragma unroll
        for (int nb = 0; nb < 8; nb++)
#pragma unroll
            for (int d = 0; d < 4; d++) ctx[mb][nb][d] = 0.f;

    const int ar = wid * 32 + (lane & 15);
    const int acoff = (lane >> 4) * 8;
    const int kr = (lane & 7) + ((lane >> 4) << 3);
    const int kcoff = ((lane >> 3) & 1) * 8;
    const int vr = lane & 15;
    const int vcoff = (lane >> 4) * 8;
    const int qrow0 = q0 + wid * 32 + (lane >> 2);

    uint32_t qf[4][2][4];   // [kstep][mb] Q fragments (persistent)

    for (int t = 0; t < ntiles; t++) {
        if (t + 1 < ntiles) {
            load_kv(t + 1, (t + 1) & 1);
            CP_COMMIT();
            CP_WAIT(1);
        } else {
            CP_WAIT(0);
        }
        __syncthreads();

        if (t == 0) {
#pragma unroll
            for (int ks = 0; ks < 4; ks++)
#pragma unroll
                for (int mb = 0; mb < 2; mb++)
                    ldsm4(qf[ks][mb],
                          sQ + (uint32_t)((ar + mb * 16) * FSTR + ks * 16 + acoff) * 2);
        }

        uint32_t base = sKV + (t & 1) * F_STAGE;
        uint32_t sKh = base, sKl = base + FKVH;
        uint32_t sVh = base + 2 * FKVH, sVl = base + 3 * FKVH;

        // S = Q @ K^T  (scale folded into Q)
        float s[2][8][4];
#pragma unroll
        for (int mb = 0; mb < 2; mb++)
#pragma unroll
            for (int nb = 0; nb < 8; nb++)
#pragma unroll
                for (int d = 0; d < 4; d++) s[mb][nb][d] = 0.f;

#pragma unroll
        for (int ks = 0; ks < 4; ks++) {
#pragma unroll
            for (int nbp = 0; nbp < 4; nbp++) {
                uint32_t bh[4], bl[4];
                uint32_t off = (uint32_t)((nbp * 16 + kr) * FSTR + ks * 16 + kcoff) * 2;
                ldsm4(bh, sKh + off);
                ldsm4(bl, sKl + off);
#pragma unroll
                for (int mb = 0; mb < 2; mb++) {
#pragma unroll
                    for (int nn = 0; nn < 2; nn++) {
                        float* cc = s[mb][nbp * 2 + nn];
                        mma16816(cc, qf[ks][mb], bh + nn * 2);
                        mma16816(cc, qf[ks][mb], bl + nn * 2);
                    }
                }
            }
        }

        // causal mask
        if (t * 64 + 63 > q0 + wid * 32) {
            int cb = t * 64 + (lane & 3) * 2;
#pragma unroll
            for (int mb = 0; mb < 2; mb++)
#pragma unroll
                for (int nb = 0; nb < 8; nb++)
#pragma unroll
                    for (int h = 0; h < 2; h++)
#pragma unroll
                        for (int j = 0; j < 2; j++)
                            if (cb + nb * 8 + j > qrow0 + mb * 16 + 8 * h)
                                s[mb][nb][2 * h + j] = -1e30f;
        }

        // online softmax
#pragma unroll
        for (int mb = 0; mb < 2; mb++) {
#pragma unroll
            for (int h = 0; h < 2; h++) {
                float rm = -1e30f;
#pragma unroll
                for (int nb = 0; nb < 8; nb++)
                    rm = fmaxf(rm, fmaxf(s[mb][nb][2 * h], s[mb][nb][2 * h + 1]));
                rm = fmaxf(rm, __shfl_xor_sync(0xffffffffu, rm, 1));
                rm = fmaxf(rm, __shfl_xor_sync(0xffffffffu, rm, 2));
                float nm = fmaxf(m_i[mb][h], rm);
                float corr = __expf(m_i[mb][h] - nm);
                m_i[mb][h] = nm;
                float rs = 0.f;
#pragma unroll
                for (int nb = 0; nb < 8; nb++) {
                    float p0 = __expf(s[mb][nb][2 * h] - nm);
                    float p1 = __expf(s[mb][nb][2 * h + 1] - nm);
                    s[mb][nb][2 * h] = p0;
                    s[mb][nb][2 * h + 1] = p1;
                    rs += p0 + p1;
                }
                rs += __shfl_xor_sync(0xffffffffu, rs, 1);
                rs += __shfl_xor_sync(0xffffffffu, rs, 2);
                l_i[mb][h] = l_i[mb][h] * corr + rs;
#pragma unroll
                for (int nb = 0; nb < 8; nb++) {
                    ctx[mb][nb][2 * h] *= corr;
                    ctx[mb][nb][2 * h + 1] *= corr;
                }
            }
        }

        // P -> fp16 A fragments (hi only; V-side is corrected)
        uint32_t pf[2][4][4];
#pragma unroll
        for (int mb = 0; mb < 2; mb++)
#pragma unroll
            for (int kb = 0; kb < 4; kb++)
#pragma unroll
                for (int r = 0; r < 4; r++) {
                    int nb = kb * 2 + (r >> 1);
                    int i0 = (r & 1) * 2;
                    pf[mb][kb][r] = pack2h(__float2half(s[mb][nb][i0]),
                                           __float2half(s[mb][nb][i0 + 1]));
                }

        // ctx += P @ V
#pragma unroll
        for (int nbp = 0; nbp < 4; nbp++) {
#pragma unroll
            for (int kb = 0; kb < 4; kb++) {
                uint32_t bh[4], bl[4];
                uint32_t off = (uint32_t)((kb * 16 + vr) * FSTR + nbp * 16 + vcoff) * 2;
                ldsm4t(bh, sVh + off);
                ldsm4t(bl, sVl + off);
#pragma unroll
                for (int mb = 0; mb < 2; mb++) {
#pragma unroll
                    for (int nn = 0; nn < 2; nn++) {
                        float* cc = ctx[mb][nbp * 2 + nn];
                        mma16816(cc, pf[mb][kb], bh + nn * 2);
                        mma16816(cc, pf[mb][kb], bl + nn * 2);
                    }
                }
            }
        }
        __syncthreads();
    }

    // epilogue: ctx -> fp16 at [b, s, head*64 + d]
    const int bb = head >> 4, nnh = head & 15;
#pragma unroll
    for (int mb = 0; mb < 2; mb++)
#pragma unroll
        for (int h = 0; h < 2; h++) {
            float inv = 1.f / l_i[mb][h];
            int srow = q0 + wid * 32 + mb * 16 + (lane >> 2) + 8 * h;
            size_t rbase = (size_t)(bb * S_ + srow) * H_ + nnh * 64;
#pragma unroll
            for (int nb = 0; nb < 8; nb++) {
                int dd = nb * 8 + (lane & 3) * 2;
                *(uint32_t*)&gctx[rbase + dd] =
                    pack2h(__float2half(ctx[mb][nb][2 * h] * inv),
                           __float2half(ctx[mb][nb][2 * h + 1] * inv));
            }
        }
}

// ---------------------------------------------------------------------------
extern "C" void kernel_launch(void* const* d_in, const int* in_sizes, int n_in,
                              void* d_out, int out_size)
{
    const float* X    = (const float*)d_in[0];
    const float* Wqkv = (const float*)d_in[2];
    const float* bqkv = (const float*)d_in[3];
    const float* Wd   = (const float*)d_in[4];
    const float* bd   = (const float*)d_in[5];
    float* out = (float*)d_out;

    convX<<<4096, 256>>>(X);
    convW<3072><<<dim3(96, 32), dim3(32, 8)>>>(Wqkv);
    convW<1024><<<dim3(32, 32), dim3(32, 8)>>>(Wd);

    cudaFuncSetAttribute(gemm_mma<0>, cudaFuncAttributeMaxDynamicSharedMemorySize, GEMM_SMEM);
    gemm_mma<0><<<dim3(24, 32), 128, GEMM_SMEM>>>(bqkv, nullptr);

    cudaFuncSetAttribute(flash_mma, cudaFuncAttributeMaxDynamicSharedMemorySize, FLASH_SMEM);
    flash_mma<<<dim3(16, 32), 128, FLASH_SMEM>>>();

    cudaFuncSetAttribute(gemm_mma<1>, cudaFuncAttributeMaxDynamicSharedMemorySize, GEMM_SMEM);
    gemm_mma<1><<<dim3(8, 32), 128, GEMM_SMEM>>>(bd, out);
}